// round 2
// baseline (speedup 1.0000x reference)
#include <cuda_runtime.h>
#include <cstdint>
#include <math.h>

#define NB_ 64
#define NS_ 512
#define NHID_ 256
#define NTAGS_ 9
#define LOGITS_N (NB_ * NS_ * NTAGS_)   // 294912
#define LENS_OFF LOGITS_N               // 294912
#define LL_OFF   (LOGITS_N + NB_)       // 294976

// Scratch (device globals: no allocation allowed)
__device__ float g_xzf[NB_ * NS_ * 1024];   // x @ W_f + b_f
__device__ float g_xzb[NB_ * NS_ * 1024];   // x @ W_b + b_b
__device__ float g_hf[NB_ * NS_ * NHID_];
__device__ float g_hb[NB_ * NS_ * NHID_];

__device__ __forceinline__ float sigmoidf_(float x) { return 1.0f / (1.0f + expf(-x)); }

// ---------------------------------------------------------------------------
// K1: fused embedding-gather + input GEMM.
// Z[r, :] = emb[text[r]] @ W + b  for both directions.
// M = 32768 (B*S), K = 128 (EMB), N = 1024 per direction.
// Grid: (512, 32): x = M tile (64 rows), y<16 -> fwd cols, y>=16 -> bwd cols.
// ---------------------------------------------------------------------------
__global__ void k_ingemm(const int* __restrict__ text, const float* __restrict__ emb,
                         const float* __restrict__ Wf, const float* __restrict__ bf,
                         const float* __restrict__ Wb, const float* __restrict__ bb)
{
    extern __shared__ float sm1[];
    float* As = sm1;               // 64 x 132 (padded)
    float* Bs = sm1 + 64 * 132;    // 128 x 64
    int*   toks = (int*)(Bs + 128 * 64);  // 64

    int bx = blockIdx.x, by = blockIdx.y, tid = threadIdx.x;
    const float* W; const float* bias; float* out; int ncol0;
    if (by < 16) { W = Wf; bias = bf; out = g_xzf; ncol0 = by * 64; }
    else         { W = Wb; bias = bb; out = g_xzb; ncol0 = (by - 16) * 64; }

    if (tid < 64) toks[tid] = text[bx * 64 + tid];
    __syncthreads();

    // A tile: 64 rows x 128 (gathered embedding rows), padded stride 132
    for (int i = tid; i < 2048; i += 256) {
        int m = i >> 5, k4 = i & 31;
        float4 v = __ldg((const float4*)(emb + (size_t)toks[m] * 128) + k4);
        *(float4*)(As + m * 132 + k4 * 4) = v;
    }
    // B tile: 128 x 64
    for (int i = tid; i < 2048; i += 256) {
        int k = i >> 4, n4 = i & 15;
        float4 v = __ldg((const float4*)(W + (size_t)k * 1024 + ncol0) + n4);
        *(float4*)(Bs + k * 64 + n4 * 4) = v;
    }
    __syncthreads();

    int tx = tid & 15, ty = tid >> 4;
    float acc[4][4];
#pragma unroll
    for (int i = 0; i < 4; i++)
#pragma unroll
        for (int q = 0; q < 4; q++) acc[i][q] = 0.0f;

#pragma unroll 4
    for (int k = 0; k < 128; k++) {
        float4 bv = *(const float4*)(Bs + k * 64 + tx * 4);
        float a0 = As[(ty * 4 + 0) * 132 + k];
        float a1 = As[(ty * 4 + 1) * 132 + k];
        float a2 = As[(ty * 4 + 2) * 132 + k];
        float a3 = As[(ty * 4 + 3) * 132 + k];
        acc[0][0] = fmaf(a0, bv.x, acc[0][0]); acc[0][1] = fmaf(a0, bv.y, acc[0][1]);
        acc[0][2] = fmaf(a0, bv.z, acc[0][2]); acc[0][3] = fmaf(a0, bv.w, acc[0][3]);
        acc[1][0] = fmaf(a1, bv.x, acc[1][0]); acc[1][1] = fmaf(a1, bv.y, acc[1][1]);
        acc[1][2] = fmaf(a1, bv.z, acc[1][2]); acc[1][3] = fmaf(a1, bv.w, acc[1][3]);
        acc[2][0] = fmaf(a2, bv.x, acc[2][0]); acc[2][1] = fmaf(a2, bv.y, acc[2][1]);
        acc[2][2] = fmaf(a2, bv.z, acc[2][2]); acc[2][3] = fmaf(a2, bv.w, acc[2][3]);
        acc[3][0] = fmaf(a3, bv.x, acc[3][0]); acc[3][1] = fmaf(a3, bv.y, acc[3][1]);
        acc[3][2] = fmaf(a3, bv.z, acc[3][2]); acc[3][3] = fmaf(a3, bv.w, acc[3][3]);
    }

    float4 bvv = *(const float4*)(bias + ncol0 + tx * 4);
#pragma unroll
    for (int i = 0; i < 4; i++) {
        float4 o;
        o.x = acc[i][0] + bvv.x; o.y = acc[i][1] + bvv.y;
        o.z = acc[i][2] + bvv.z; o.w = acc[i][3] + bvv.w;
        *(float4*)(out + (size_t)(bx * 64 + ty * 4 + i) * 1024 + ncol0 + tx * 4) = o;
    }
}

// ---------------------------------------------------------------------------
// K2: LSTM recurrence, both directions.
// 16 clusters of 8 CTAs (cluster c: dir = c&1, batch group = c>>1, 8 rows).
// Each CTA owns 32 hidden units (gate cols {j, 256+j, 512+j, 768+j}),
// keeps its U slice (256x128 f32 = 128KB) in SMEM for all 512 steps.
// h (8x256) replicated per CTA, double-buffered; new h chunks pushed to all
// cluster CTAs via DSMEM, one barrier.cluster per step.
// ---------------------------------------------------------------------------
__global__ void __cluster_dims__(8, 1, 1) k_lstm(const float* __restrict__ Uf,
                                                 const float* __restrict__ Ub)
{
    extern __shared__ float sm2[];
    float* Uc = sm2;                    // 256*128
    float* hb = sm2 + 32768;            // 2 * 8 * 256
    float* zp = sm2 + 32768 + 4096;     // 8 * 8 * 128

    int tid = threadIdx.x;
    unsigned rank;
    asm("mov.u32 %0, %%cluster_ctarank;" : "=r"(rank));
    int cl = blockIdx.x >> 3;
    int dir = cl & 1, bg = cl >> 1;
    const float* U    = dir ? Ub     : Uf;
    const float* xz   = dir ? g_xzb  : g_xzf;
    float*       hout = dir ? g_hb   : g_hf;

    // Load U slice: Uc[k][g*32+j] = U[k][g*256 + rank*32 + j]
    for (int idx = tid; idx < 32768; idx += 256) {
        int k = idx >> 7, gc = idx & 127;
        Uc[idx] = __ldg(U + (size_t)k * 1024 + (gc >> 5) * 256 + rank * 32 + (gc & 31));
    }
    for (int idx = tid; idx < 4096; idx += 256) hb[idx] = 0.0f;
    asm volatile("barrier.cluster.arrive.aligned;\n\tbarrier.cluster.wait.aligned;" ::: "memory");

    int w = tid >> 5, l = tid & 31;
    int bloc = w, jj = l;                  // consumer mapping: (batch row, hidden j)
    int bglob = bg * 8 + bloc;
    float cst = 0.0f;
    uint32_t hb_addr = (uint32_t)__cvta_generic_to_shared(hb);

    for (int n = 0; n < 512; n++) {
        int cur = n & 1, nxt = cur ^ 1;
        int t = dir ? (511 - n) : n;

        // Prefetch this step's xz (independent of h; lands during GEMM)
        const float* xp = xz + ((size_t)bglob * 512 + t) * 1024 + rank * 32 + jj;
        float x0 = __ldg(xp);       float x1 = __ldg(xp + 256);
        float x2 = __ldg(xp + 512); float x3 = __ldg(xp + 768);

        // GEMM: z[8][128] = h[8][256] @ Uc[256][128], K split across 8 warps
        const float4* U4 = (const float4*)Uc;
        const float4* H4 = (const float4*)(hb + cur * 2048);
        float acc[8][4];
#pragma unroll
        for (int b = 0; b < 8; b++) { acc[b][0] = 0.f; acc[b][1] = 0.f; acc[b][2] = 0.f; acc[b][3] = 0.f; }
        int k0 = w * 32;
#pragma unroll
        for (int kk = 0; kk < 32; kk += 4) {
            int kb = k0 + kk;
            float4 u0 = U4[(kb + 0) * 32 + l];
            float4 u1 = U4[(kb + 1) * 32 + l];
            float4 u2 = U4[(kb + 2) * 32 + l];
            float4 u3 = U4[(kb + 3) * 32 + l];
#pragma unroll
            for (int b = 0; b < 8; b++) {
                float4 hv4 = H4[b * 64 + (kb >> 2)];
                acc[b][0] = fmaf(hv4.x, u0.x, acc[b][0]); acc[b][1] = fmaf(hv4.x, u0.y, acc[b][1]);
                acc[b][2] = fmaf(hv4.x, u0.z, acc[b][2]); acc[b][3] = fmaf(hv4.x, u0.w, acc[b][3]);
                acc[b][0] = fmaf(hv4.y, u1.x, acc[b][0]); acc[b][1] = fmaf(hv4.y, u1.y, acc[b][1]);
                acc[b][2] = fmaf(hv4.y, u1.z, acc[b][2]); acc[b][3] = fmaf(hv4.y, u1.w, acc[b][3]);
                acc[b][0] = fmaf(hv4.z, u2.x, acc[b][0]); acc[b][1] = fmaf(hv4.z, u2.y, acc[b][1]);
                acc[b][2] = fmaf(hv4.z, u2.z, acc[b][2]); acc[b][3] = fmaf(hv4.z, u2.w, acc[b][3]);
                acc[b][0] = fmaf(hv4.w, u3.x, acc[b][0]); acc[b][1] = fmaf(hv4.w, u3.y, acc[b][1]);
                acc[b][2] = fmaf(hv4.w, u3.z, acc[b][2]); acc[b][3] = fmaf(hv4.w, u3.w, acc[b][3]);
            }
        }
#pragma unroll
        for (int b = 0; b < 8; b++)
            *(float4*)(zp + w * 1024 + b * 128 + l * 4) =
                make_float4(acc[b][0], acc[b][1], acc[b][2], acc[b][3]);
        __syncthreads();

        // Gate math: thread (bloc, jj) owns one hidden state element
        float zi = 0.f, zf = 0.f, zg = 0.f, zo = 0.f;
#pragma unroll
        for (int w2 = 0; w2 < 8; w2++) {
            const float* zz = zp + w2 * 1024 + bloc * 128;
            zi += zz[jj]; zf += zz[32 + jj]; zg += zz[64 + jj]; zo += zz[96 + jj];
        }
        float ig = sigmoidf_(zi + x0);
        float fg = sigmoidf_(zf + x1);
        float gg = tanhf(zg + x2);
        float og = sigmoidf_(zo + x3);
        cst = fg * cst + ig * gg;
        float hnew = og * tanhf(cst);

        hout[((size_t)bglob * 512 + t) * 256 + rank * 32 + jj] = hnew;

        // Push h element into every cluster CTA's next buffer (DSMEM)
        uint32_t loff = hb_addr + (uint32_t)((nxt * 2048 + bloc * 256 + rank * 32 + jj) * 4);
#pragma unroll
        for (int dc = 0; dc < 8; dc++) {
            uint32_t ra;
            asm volatile("mapa.shared::cluster.u32 %0, %1, %2;" : "=r"(ra) : "r"(loff), "r"(dc));
            asm volatile("st.shared::cluster.f32 [%0], %1;" :: "r"(ra), "f"(hnew));
        }
        asm volatile("barrier.cluster.arrive.aligned;\n\tbarrier.cluster.wait.aligned;" ::: "memory");
    }
}

// ---------------------------------------------------------------------------
// K3: logits = [h_fwd ; h_bwd] @ W_d + b_d.  Warp per row, W_d^T in smem.
// ---------------------------------------------------------------------------
__global__ void k_logits(const float* __restrict__ Wd, const float* __restrict__ bd,
                         float* __restrict__ out)
{
    __shared__ float Wds[NTAGS_ * 512];
    __shared__ float bds[NTAGS_];
    int tid = threadIdx.x;
    for (int i = tid; i < 512 * NTAGS_; i += 256) {
        int k = i / NTAGS_, c = i - k * NTAGS_;
        Wds[c * 512 + k] = Wd[i];
    }
    if (tid < NTAGS_) bds[tid] = bd[tid];
    __syncthreads();

    int wid = tid >> 5, l = tid & 31;
    int r = blockIdx.x * 8 + wid;
    const float* pf = g_hf + (size_t)r * 256 + l;
    const float* pb = g_hb + (size_t)r * 256 + l;
    float hf[8], hbv[8];
#pragma unroll
    for (int i = 0; i < 8; i++) { hf[i] = pf[32 * i]; hbv[i] = pb[32 * i]; }

    float parts[NTAGS_];
#pragma unroll
    for (int c = 0; c < NTAGS_; c++) {
        float p = 0.f;
#pragma unroll
        for (int i = 0; i < 8; i++) {
            p = fmaf(hf[i],  Wds[c * 512 + 32 * i + l], p);
            p = fmaf(hbv[i], Wds[c * 512 + 256 + 32 * i + l], p);
        }
        parts[c] = p;
    }
#pragma unroll
    for (int c = 0; c < NTAGS_; c++)
#pragma unroll
        for (int off = 16; off; off >>= 1)
            parts[c] += __shfl_xor_sync(0xffffffffu, parts[c], off);

    if (l == 0) {
#pragma unroll
        for (int c = 0; c < NTAGS_; c++)
            out[(size_t)r * NTAGS_ + c] = parts[c] + bds[c];
    }
}

// ---------------------------------------------------------------------------
// K4: lens + CRF (sequence score and log-norm).  One warp per batch element.
// ---------------------------------------------------------------------------
__global__ void k_crf(const int* __restrict__ text, const int* __restrict__ labels,
                      const float* __restrict__ trans, float* __restrict__ out)
{
    int b = blockIdx.x;
    int l = threadIdx.x;
    const float* lgb = out + (size_t)b * NS_ * NTAGS_;
    const int*   lab = labels + b * NS_;

    // lens
    int cnt = 0;
#pragma unroll
    for (int i = 0; i < 16; i++) cnt += (text[b * NS_ + l + 32 * i] != 0) ? 1 : 0;
#pragma unroll
    for (int off = 16; off; off >>= 1) cnt += __shfl_xor_sync(0xffffffffu, cnt, off);
    int len = cnt;
    if (l == 0) out[LENS_OFF + b] = (float)len;

    // sequence score: unary + binary
    float sc = 0.f;
#pragma unroll
    for (int i = 0; i < 16; i++) {
        int s = l + 32 * i;
        if (s < len)     sc += lgb[s * NTAGS_ + lab[s]];
        if (s < len - 1) sc += trans[lab[s] * NTAGS_ + lab[s + 1]];
    }
#pragma unroll
    for (int off = 16; off; off >>= 1) sc += __shfl_xor_sync(0xffffffffu, sc, off);

    // alpha recurrence: lane j<9 owns alpha[j]; tc[i] = trans[i][j]
    int j = l;
    float tc[NTAGS_];
#pragma unroll
    for (int i = 0; i < NTAGS_; i++) tc[i] = trans[i * NTAGS_ + ((j < NTAGS_) ? j : 0)];
    float alpha = (j < NTAGS_) ? lgb[j] : -3.0e38f;

    float lt_next = (j < NTAGS_) ? lgb[NTAGS_ + j] : 0.f;
    for (int t = 1; t < NS_; t++) {
        float lt = lt_next;
        if (t + 1 < NS_) lt_next = (j < NTAGS_) ? lgb[(t + 1) * NTAGS_ + j] : 0.f;
        float vv[NTAGS_];
        float mx = -3.0e38f;
#pragma unroll
        for (int i = 0; i < NTAGS_; i++) {
            float ai = __shfl_sync(0xffffffffu, alpha, i);
            vv[i] = ai + tc[i];
            mx = fmaxf(mx, vv[i]);
        }
        float sume = 0.f;
#pragma unroll
        for (int i = 0; i < NTAGS_; i++) sume += expf(vv[i] - mx);
        float na = mx + logf(sume) + lt;
        if ((t < len) && (j < NTAGS_)) alpha = na;
    }

    // final logsumexp over tags
    float a = (j < NTAGS_) ? alpha : -3.0e38f;
    float mx = a;
#pragma unroll
    for (int off = 16; off; off >>= 1) mx = fmaxf(mx, __shfl_xor_sync(0xffffffffu, mx, off));
    float e = (j < NTAGS_) ? expf(a - mx) : 0.f;
#pragma unroll
    for (int off = 16; off; off >>= 1) e += __shfl_xor_sync(0xffffffffu, e, off);
    float lse = mx + logf(e);

    if (l == 0) out[LL_OFF + b] = sc - lse;
}

// ---------------------------------------------------------------------------
extern "C" void kernel_launch(void* const* d_in, const int* in_sizes, int n_in,
                              void* d_out, int out_size)
{
    (void)in_sizes; (void)n_in; (void)out_size;
    const int*   text   = (const int*)d_in[0];
    const int*   labels = (const int*)d_in[1];
    const float* emb    = (const float*)d_in[2];
    const float* Wf     = (const float*)d_in[3];
    const float* Uf     = (const float*)d_in[4];
    const float* bf     = (const float*)d_in[5];
    const float* Wb     = (const float*)d_in[6];
    const float* Ub     = (const float*)d_in[7];
    const float* bb     = (const float*)d_in[8];
    const float* Wd     = (const float*)d_in[9];
    const float* bd     = (const float*)d_in[10];
    const float* trans  = (const float*)d_in[11];
    float* out = (float*)d_out;

    int smem1 = (64 * 132 + 128 * 64) * 4 + 64 * 4;
    cudaFuncSetAttribute(k_ingemm, cudaFuncAttributeMaxDynamicSharedMemorySize, smem1);
    int smem2 = (32768 + 4096 + 8192) * 4;
    cudaFuncSetAttribute(k_lstm, cudaFuncAttributeMaxDynamicSharedMemorySize, smem2);

    k_ingemm<<<dim3(512, 32), 256, smem1>>>(text, emb, Wf, bf, Wb, bb);
    k_lstm<<<128, 256, smem2>>>(Uf, Ub);
    k_logits<<<4096, 256>>>(Wd, bd, out);
    k_crf<<<NB_, 32>>>(text, labels, trans, out);
}

// round 3
// speedup vs baseline: 1.0697x; 1.0697x over previous
#include <cuda_runtime.h>
#include <cstdint>
#include <math.h>

#define NB_ 64
#define NS_ 512
#define NHID_ 256
#define NTAGS_ 9
#define LOGITS_N (NB_ * NS_ * NTAGS_)   // 294912
#define LENS_OFF LOGITS_N               // 294912
#define LL_OFF   (LOGITS_N + NB_)       // 294976

// Scratch (device globals: no allocation allowed)
__device__ float g_xzf[NB_ * NS_ * 1024];   // x @ W_f + b_f
__device__ float g_xzb[NB_ * NS_ * 1024];   // x @ W_b + b_b
__device__ float g_hf[NB_ * NS_ * NHID_];
__device__ float g_hb[NB_ * NS_ * NHID_];

// ---------------- packed f32x2 helpers (sm_103a FFMA2 path) ----------------
__device__ __forceinline__ unsigned long long pk2(float lo, float hi) {
    unsigned long long r;
    asm("mov.b64 %0, {%1, %2};" : "=l"(r) : "f"(lo), "f"(hi));
    return r;
}
__device__ __forceinline__ float2 unpk2(unsigned long long v) {
    float2 r;
    asm("mov.b64 {%0, %1}, %2;" : "=f"(r.x), "=f"(r.y) : "l"(v));
    return r;
}
__device__ __forceinline__ unsigned long long fma2_(unsigned long long a,
                                                    unsigned long long b,
                                                    unsigned long long c) {
    unsigned long long d;
    asm("fma.rn.f32x2 %0, %1, %2, %3;" : "=l"(d) : "l"(a), "l"(b), "l"(c));
    return d;
}
__device__ __forceinline__ unsigned long long add2_(unsigned long long a,
                                                    unsigned long long b) {
    unsigned long long d;
    asm("add.rn.f32x2 %0, %1, %2;" : "=l"(d) : "l"(a), "l"(b));
    return d;
}

__device__ __forceinline__ float fsig(float x) {
    return __fdividef(1.0f, 1.0f + __expf(-x));
}
__device__ __forceinline__ float ftanh_(float x) {
    x = fminf(fmaxf(x, -15.0f), 15.0f);
    float e = __expf(2.0f * x);
    return __fdividef(e - 1.0f, e + 1.0f);
}

// ---------------------------------------------------------------------------
// K1: fused embedding-gather + input GEMM (FFMA2 inner loop).
// Z[r, :] = emb[text[r]] @ W + b  for both directions.
// Grid: (512, 32): x = M tile (64 rows), y<16 -> fwd cols, y>=16 -> bwd cols.
// ---------------------------------------------------------------------------
__global__ void k_ingemm(const int* __restrict__ text, const float* __restrict__ emb,
                         const float* __restrict__ Wf, const float* __restrict__ bf,
                         const float* __restrict__ Wb, const float* __restrict__ bb)
{
    extern __shared__ float sm1[];
    float* As = sm1;               // 64 x 132 (padded)
    float* Bs = sm1 + 64 * 132;    // 128 x 64
    int*   toks = (int*)(Bs + 128 * 64);  // 64

    int bx = blockIdx.x, by = blockIdx.y, tid = threadIdx.x;
    const float* W; const float* bias; float* out; int ncol0;
    if (by < 16) { W = Wf; bias = bf; out = g_xzf; ncol0 = by * 64; }
    else         { W = Wb; bias = bb; out = g_xzb; ncol0 = (by - 16) * 64; }

    if (tid < 64) toks[tid] = text[bx * 64 + tid];
    __syncthreads();

    for (int i = tid; i < 2048; i += 256) {
        int m = i >> 5, k4 = i & 31;
        float4 v = __ldg((const float4*)(emb + (size_t)toks[m] * 128) + k4);
        *(float4*)(As + m * 132 + k4 * 4) = v;
    }
    for (int i = tid; i < 2048; i += 256) {
        int k = i >> 4, n4 = i & 15;
        float4 v = __ldg((const float4*)(W + (size_t)k * 1024 + ncol0) + n4);
        *(float4*)(Bs + k * 64 + n4 * 4) = v;
    }
    __syncthreads();

    int tx = tid & 15, ty = tid >> 4;
    unsigned long long a01[4], a23[4];
#pragma unroll
    for (int i = 0; i < 4; i++) { a01[i] = 0ULL; a23[i] = 0ULL; }

#pragma unroll 2
    for (int kb = 0; kb < 128; kb += 4) {
        float4 av[4];
#pragma unroll
        for (int i = 0; i < 4; i++)
            av[i] = *(const float4*)(As + (ty * 4 + i) * 132 + kb);
#pragma unroll
        for (int kq = 0; kq < 4; kq++) {
            float4 bv = *(const float4*)(Bs + (kb + kq) * 64 + tx * 4);
            unsigned long long b01 = pk2(bv.x, bv.y);
            unsigned long long b23 = pk2(bv.z, bv.w);
#pragma unroll
            for (int i = 0; i < 4; i++) {
                float a = (kq == 0) ? av[i].x : (kq == 1) ? av[i].y
                         : (kq == 2) ? av[i].z : av[i].w;
                unsigned long long aa = pk2(a, a);
                a01[i] = fma2_(aa, b01, a01[i]);
                a23[i] = fma2_(aa, b23, a23[i]);
            }
        }
    }

    float4 bvv = *(const float4*)(bias + ncol0 + tx * 4);
#pragma unroll
    for (int i = 0; i < 4; i++) {
        float2 p01 = unpk2(a01[i]), p23 = unpk2(a23[i]);
        float4 o;
        o.x = p01.x + bvv.x; o.y = p01.y + bvv.y;
        o.z = p23.x + bvv.z; o.w = p23.y + bvv.w;
        *(float4*)(out + (size_t)(bx * 64 + ty * 4 + i) * 1024 + ncol0 + tx * 4) = o;
    }
}

// ---------------------------------------------------------------------------
// K2: LSTM recurrence, both directions. 16 clusters of 8 CTAs.
// CTA owns 32 hidden units; U slice (256 x 128, gate-interleaved columns
// c = jj*4 + gate) in SMEM (128 KB). 512 threads: 16 warps each do a K=16
// slice of z[8][128] = h[8][256] @ Uc with packed FFMA2; partials reduced
// in SMEM; 256 consumer threads do gates + DSMEM h broadcast.
// ---------------------------------------------------------------------------
__global__ void __cluster_dims__(8, 1, 1) __launch_bounds__(512, 1)
k_lstm(const float* __restrict__ Uf, const float* __restrict__ Ub)
{
    extern __shared__ float sm2[];
    float* Uc = sm2;                    // 256*128  (col c = jj*4 + gate)
    float* hb = sm2 + 32768;            // 2 * 8 * 256
    float* zp = sm2 + 32768 + 4096;     // 16 * 8 * 128

    int tid = threadIdx.x;
    unsigned rank;
    asm("mov.u32 %0, %%cluster_ctarank;" : "=r"(rank));
    int cl = blockIdx.x >> 3;
    int dir = cl & 1, bg = cl >> 1;
    const float* U    = dir ? Ub     : Uf;
    const float* xz   = dir ? g_xzb  : g_xzf;
    float*       hout = dir ? g_hb   : g_hf;

    // Load U slice with gate-interleaved columns:
    // Uc[k*128 + jj*4 + g] = U[k*1024 + g*256 + rank*32 + jj]
    for (int idx = tid; idx < 32768; idx += 512) {
        int k = idx >> 7, c = idx & 127;
        int jj = c >> 2, g = c & 3;
        Uc[idx] = __ldg(U + (size_t)k * 1024 + g * 256 + rank * 32 + jj);
    }
    for (int idx = tid; idx < 4096; idx += 512) hb[idx] = 0.0f;
    asm volatile("barrier.cluster.arrive.aligned;\n\tbarrier.cluster.wait.aligned;" ::: "memory");

    int w = tid >> 5, l = tid & 31;
    int bloc = (tid >> 5) & 7, jj = l;     // consumer mapping (tid < 256)
    int bglob = bg * 8 + bloc;
    bool cons = (tid < 256);
    float cst = 0.0f;
    uint32_t hb_addr = (uint32_t)__cvta_generic_to_shared(hb);

    const float4* U4 = (const float4*)Uc;

    for (int n = 0; n < 512; n++) {
        int cur = n & 1, nxt = cur ^ 1;
        int t = dir ? (511 - n) : n;

        // Prefetch this step's xz (consumers only; lands during GEMM)
        float x0 = 0.f, x1 = 0.f, x2 = 0.f, x3 = 0.f;
        if (cons) {
            const float* xp = xz + ((size_t)bglob * 512 + t) * 1024 + rank * 32 + jj;
            x0 = __ldg(xp);       x1 = __ldg(xp + 256);
            x2 = __ldg(xp + 512); x3 = __ldg(xp + 768);
        }

        // GEMM: z[8][128] = h[8][256] @ Uc[256][128], K split across 16 warps
        const float4* H4 = (const float4*)(hb + cur * 2048);
        unsigned long long acc01[8], acc23[8];
#pragma unroll
        for (int b = 0; b < 8; b++) { acc01[b] = 0ULL; acc23[b] = 0ULL; }
        int k0 = w * 16;
#pragma unroll
        for (int kk = 0; kk < 16; kk += 4) {
            int kb = k0 + kk;
            float4 h4[8];
#pragma unroll
            for (int b = 0; b < 8; b++) h4[b] = H4[b * 64 + (kb >> 2)];
#pragma unroll
            for (int kq = 0; kq < 4; kq++) {
                float4 u = U4[(kb + kq) * 32 + l];
                unsigned long long u01 = pk2(u.x, u.y);
                unsigned long long u23 = pk2(u.z, u.w);
#pragma unroll
                for (int b = 0; b < 8; b++) {
                    float hv = (kq == 0) ? h4[b].x : (kq == 1) ? h4[b].y
                             : (kq == 2) ? h4[b].z : h4[b].w;
                    unsigned long long hh = pk2(hv, hv);
                    acc01[b] = fma2_(hh, u01, acc01[b]);
                    acc23[b] = fma2_(hh, u23, acc23[b]);
                }
            }
        }
#pragma unroll
        for (int b = 0; b < 8; b++) {
            float2 p01 = unpk2(acc01[b]), p23 = unpk2(acc23[b]);
            *(float4*)(zp + w * 1024 + b * 128 + l * 4) =
                make_float4(p01.x, p01.y, p23.x, p23.y);
        }
        __syncthreads();

        if (cons) {
            // Reduce 16 partials: cols jj*4..jj*4+3 = gates i,f,g,o for unit jj
            unsigned long long s01 = 0ULL, s23 = 0ULL;
#pragma unroll
            for (int w2 = 0; w2 < 16; w2++) {
                float4 v = *(const float4*)(zp + w2 * 1024 + bloc * 128 + jj * 4);
                s01 = add2_(s01, pk2(v.x, v.y));
                s23 = add2_(s23, pk2(v.z, v.w));
            }
            float2 zif = unpk2(s01), zgo = unpk2(s23);
            float ig = fsig(zif.x + x0);
            float fg = fsig(zif.y + x1);
            float gg = ftanh_(zgo.x + x2);
            float og = fsig(zgo.y + x3);
            cst = fg * cst + ig * gg;
            float hnew = og * ftanh_(cst);

            hout[((size_t)bglob * 512 + t) * 256 + rank * 32 + jj] = hnew;

            // Push h element into every cluster CTA's next buffer (DSMEM)
            uint32_t loff = hb_addr + (uint32_t)((nxt * 2048 + bloc * 256 + rank * 32 + jj) * 4);
#pragma unroll
            for (int dc = 0; dc < 8; dc++) {
                uint32_t ra;
                asm volatile("mapa.shared::cluster.u32 %0, %1, %2;" : "=r"(ra) : "r"(loff), "r"(dc));
                asm volatile("st.shared::cluster.f32 [%0], %1;" :: "r"(ra), "f"(hnew));
            }
        }
        asm volatile("barrier.cluster.arrive.aligned;\n\tbarrier.cluster.wait.aligned;" ::: "memory");
    }
}

// ---------------------------------------------------------------------------
// K3: logits = [h_fwd ; h_bwd] @ W_d + b_d.  Warp per row, W_d^T in smem.
// ---------------------------------------------------------------------------
__global__ void k_logits(const float* __restrict__ Wd, const float* __restrict__ bd,
                         float* __restrict__ out)
{
    __shared__ float Wds[NTAGS_ * 512];
    __shared__ float bds[NTAGS_];
    int tid = threadIdx.x;
    for (int i = tid; i < 512 * NTAGS_; i += 256) {
        int k = i / NTAGS_, c = i - k * NTAGS_;
        Wds[c * 512 + k] = Wd[i];
    }
    if (tid < NTAGS_) bds[tid] = bd[tid];
    __syncthreads();

    int wid = tid >> 5, l = tid & 31;
    int r = blockIdx.x * 8 + wid;
    const float* pf = g_hf + (size_t)r * 256 + l;
    const float* pb = g_hb + (size_t)r * 256 + l;
    float hf[8], hbv[8];
#pragma unroll
    for (int i = 0; i < 8; i++) { hf[i] = pf[32 * i]; hbv[i] = pb[32 * i]; }

    float parts[NTAGS_];
#pragma unroll
    for (int c = 0; c < NTAGS_; c++) {
        float p = 0.f;
#pragma unroll
        for (int i = 0; i < 8; i++) {
            p = fmaf(hf[i],  Wds[c * 512 + 32 * i + l], p);
            p = fmaf(hbv[i], Wds[c * 512 + 256 + 32 * i + l], p);
        }
        parts[c] = p;
    }
#pragma unroll
    for (int c = 0; c < NTAGS_; c++)
#pragma unroll
        for (int off = 16; off; off >>= 1)
            parts[c] += __shfl_xor_sync(0xffffffffu, parts[c], off);

    if (l == 0) {
#pragma unroll
        for (int c = 0; c < NTAGS_; c++)
            out[(size_t)r * NTAGS_ + c] = parts[c] + bds[c];
    }
}

// ---------------------------------------------------------------------------
// K4: lens + CRF.  One warp per batch element; fast-math exp/log.
// ---------------------------------------------------------------------------
__global__ void k_crf(const int* __restrict__ text, const int* __restrict__ labels,
                      const float* __restrict__ trans, float* __restrict__ out)
{
    int b = blockIdx.x;
    int l = threadIdx.x;
    const float* lgb = out + (size_t)b * NS_ * NTAGS_;
    const int*   lab = labels + b * NS_;

    // lens
    int cnt = 0;
#pragma unroll
    for (int i = 0; i < 16; i++) cnt += (text[b * NS_ + l + 32 * i] != 0) ? 1 : 0;
#pragma unroll
    for (int off = 16; off; off >>= 1) cnt += __shfl_xor_sync(0xffffffffu, cnt, off);
    int len = cnt;
    if (l == 0) out[LENS_OFF + b] = (float)len;

    // sequence score: unary + binary
    float sc = 0.f;
#pragma unroll
    for (int i = 0; i < 16; i++) {
        int s = l + 32 * i;
        if (s < len)     sc += lgb[s * NTAGS_ + lab[s]];
        if (s < len - 1) sc += trans[lab[s] * NTAGS_ + lab[s + 1]];
    }
#pragma unroll
    for (int off = 16; off; off >>= 1) sc += __shfl_xor_sync(0xffffffffu, sc, off);

    // alpha recurrence: lane j<9 owns alpha[j]; tc[i] = trans[i][j]
    int j = l;
    float tc[NTAGS_];
#pragma unroll
    for (int i = 0; i < NTAGS_; i++) tc[i] = trans[i * NTAGS_ + ((j < NTAGS_) ? j : 0)];
    float alpha = (j < NTAGS_) ? lgb[j] : -3.0e38f;

    float lt_next = (j < NTAGS_) ? lgb[NTAGS_ + j] : 0.f;
    for (int t = 1; t < NS_; t++) {
        float lt = lt_next;
        if (t + 1 < NS_) lt_next = (j < NTAGS_) ? lgb[(t + 1) * NTAGS_ + j] : 0.f;
        float vv[NTAGS_];
#pragma unroll
        for (int i = 0; i < NTAGS_; i++) {
            float ai = __shfl_sync(0xffffffffu, alpha, i);
            vv[i] = ai + tc[i];
        }
        // pairwise max tree
        float m01 = fmaxf(vv[0], vv[1]), m23 = fmaxf(vv[2], vv[3]);
        float m45 = fmaxf(vv[4], vv[5]), m67 = fmaxf(vv[6], vv[7]);
        float m03 = fmaxf(m01, m23), m47 = fmaxf(m45, m67);
        float mx = fmaxf(fmaxf(m03, m47), vv[8]);
        float e0 = __expf(vv[0] - mx) + __expf(vv[1] - mx);
        float e1 = __expf(vv[2] - mx) + __expf(vv[3] - mx);
        float e2 = __expf(vv[4] - mx) + __expf(vv[5] - mx);
        float e3 = __expf(vv[6] - mx) + __expf(vv[7] - mx);
        float sume = ((e0 + e1) + (e2 + e3)) + __expf(vv[8] - mx);
        float na = mx + __logf(sume) + lt;
        if ((t < len) && (j < NTAGS_)) alpha = na;
    }

    // final logsumexp over tags
    float a = (j < NTAGS_) ? alpha : -3.0e38f;
    float mx = a;
#pragma unroll
    for (int off = 16; off; off >>= 1) mx = fmaxf(mx, __shfl_xor_sync(0xffffffffu, mx, off));
    float e = (j < NTAGS_) ? __expf(a - mx) : 0.f;
#pragma unroll
    for (int off = 16; off; off >>= 1) e += __shfl_xor_sync(0xffffffffu, e, off);
    float lse = mx + __logf(e);

    if (l == 0) out[LL_OFF + b] = sc - lse;
}

// ---------------------------------------------------------------------------
extern "C" void kernel_launch(void* const* d_in, const int* in_sizes, int n_in,
                              void* d_out, int out_size)
{
    (void)in_sizes; (void)n_in; (void)out_size;
    const int*   text   = (const int*)d_in[0];
    const int*   labels = (const int*)d_in[1];
    const float* emb    = (const float*)d_in[2];
    const float* Wf     = (const float*)d_in[3];
    const float* Uf     = (const float*)d_in[4];
    const float* bf     = (const float*)d_in[5];
    const float* Wb     = (const float*)d_in[6];
    const float* Ub     = (const float*)d_in[7];
    const float* bb     = (const float*)d_in[8];
    const float* Wd     = (const float*)d_in[9];
    const float* bd     = (const float*)d_in[10];
    const float* trans  = (const float*)d_in[11];
    float* out = (float*)d_out;

    int smem1 = (64 * 132 + 128 * 64) * 4 + 64 * 4;
    cudaFuncSetAttribute(k_ingemm, cudaFuncAttributeMaxDynamicSharedMemorySize, smem1);
    int smem2 = (32768 + 4096 + 16384) * 4;   // 212 KB
    cudaFuncSetAttribute(k_lstm, cudaFuncAttributeMaxDynamicSharedMemorySize, smem2);

    k_ingemm<<<dim3(512, 32), 256, smem1>>>(text, emb, Wf, bf, Wb, bb);
    k_lstm<<<128, 512, smem2>>>(Uf, Ub);
    k_logits<<<4096, 256>>>(Wd, bd, out);
    k_crf<<<NB_, 32>>>(text, labels, trans, out);
}